// round 2
// baseline (speedup 1.0000x reference)
#include <cuda_runtime.h>
#include <math.h>

#define Hdim 768
#define Ldim 2
#define Vdim 32000
#define Bdim 128
#define Tdim 64
#define Sdim 32
#define G4   (4 * Hdim)   // 3072

// ---------------- scratch (device globals; no allocation allowed) -----------
__device__ __align__(16) float g_xs   [Tdim * Bdim * Hdim];   // (t,b,h) embedded targets
__device__ __align__(16) float g_ys0  [Tdim * Bdim * Hdim];   // layer-0 outputs
__device__ __align__(16) float g_ys1  [Tdim * Bdim * Hdim];   // layer-1 outputs
__device__ __align__(16) float g_xproj[Tdim * Bdim * G4];     // precomputed input projections (+biases)
__device__ __align__(16) float g_h    [Bdim * Hdim];
__device__ __align__(16) float g_c    [Bdim * Hdim];
__device__ __align__(16) float g_gates[Bdim * G4];

// ---------------- embeddings ------------------------------------------------
__global__ void embed_trg_kernel(const int* __restrict__ trg,
                                 const float* __restrict__ emb,
                                 float* __restrict__ xs) {
    int idx = blockIdx.x * blockDim.x + threadIdx.x;
    if (idx >= Tdim * Bdim * Hdim) return;
    int j = idx % Hdim;
    int r = idx / Hdim;        // r = t*B + b
    int b = r % Bdim;
    int t = r / Bdim;
    int tok = trg[b * Tdim + t];
    xs[idx] = emb[(size_t)tok * Hdim + j];
}

__global__ void init_h_kernel(const int* __restrict__ src,
                              const float* __restrict__ bert,
                              float* __restrict__ h,
                              float* __restrict__ c) {
    int idx = blockIdx.x * blockDim.x + threadIdx.x;
    if (idx >= Bdim * Hdim) return;
    int b = idx / Hdim, j = idx % Hdim;
    int tok = src[b * Sdim];   // src[:,0]
    h[idx] = bert[(size_t)tok * Hdim + j];
    c[idx] = 0.f;
}

// ---------------- 128x128x16 SGEMM: C = A(MxK) * Bm(NxK)^T + bias ----------
// REMAP: output row r = t*B+b gets written to out row b*T+t (for final logits).
template <bool REMAP>
__global__ void sgemm128_kernel(const float* __restrict__ A,
                                const float* __restrict__ Bm,
                                float* __restrict__ C,
                                int N, int K,
                                const float* __restrict__ bias1,
                                const float* __restrict__ bias2) {
    __shared__ float As[16][128];
    __shared__ float Bs[16][128];
    const int tid = threadIdx.x;          // 256 threads
    const int tx = tid & 15, ty = tid >> 4;
    const int m0 = blockIdx.y * 128, n0 = blockIdx.x * 128;

    float acc[8][8];
#pragma unroll
    for (int i = 0; i < 8; i++)
#pragma unroll
        for (int j = 0; j < 8; j++) acc[i][j] = 0.f;

    for (int kt = 0; kt < K; kt += 16) {
#pragma unroll
        for (int it = 0; it < 2; it++) {
            int lin = tid + it * 256;
            int r  = lin >> 2;              // 0..127
            int k4 = (lin & 3) << 2;        // 0,4,8,12
            float4 va = *reinterpret_cast<const float4*>(A + (size_t)(m0 + r) * K + kt + k4);
            As[k4 + 0][r] = va.x; As[k4 + 1][r] = va.y;
            As[k4 + 2][r] = va.z; As[k4 + 3][r] = va.w;
            float4 vb = *reinterpret_cast<const float4*>(Bm + (size_t)(n0 + r) * K + kt + k4);
            Bs[k4 + 0][r] = vb.x; Bs[k4 + 1][r] = vb.y;
            Bs[k4 + 2][r] = vb.z; Bs[k4 + 3][r] = vb.w;
        }
        __syncthreads();
#pragma unroll
        for (int k = 0; k < 16; k++) {
            float4 a0 = *reinterpret_cast<const float4*>(&As[k][ty * 8]);
            float4 a1 = *reinterpret_cast<const float4*>(&As[k][ty * 8 + 4]);
            float4 b0 = *reinterpret_cast<const float4*>(&Bs[k][tx * 8]);
            float4 b1 = *reinterpret_cast<const float4*>(&Bs[k][tx * 8 + 4]);
            float a[8] = {a0.x, a0.y, a0.z, a0.w, a1.x, a1.y, a1.z, a1.w};
            float b[8] = {b0.x, b0.y, b0.z, b0.w, b1.x, b1.y, b1.z, b1.w};
#pragma unroll
            for (int i = 0; i < 8; i++)
#pragma unroll
                for (int j = 0; j < 8; j++) acc[i][j] = fmaf(a[i], b[j], acc[i][j]);
        }
        __syncthreads();
    }

#pragma unroll
    for (int i = 0; i < 8; i++) {
        int r = m0 + ty * 8 + i;
        int orow = REMAP ? ((r & (Bdim - 1)) * Tdim + (r >> 7)) : r;
#pragma unroll
        for (int j = 0; j < 8; j++) {
            int col = n0 + tx * 8 + j;
            float bv = 0.f;
            if (bias1) bv += bias1[col];
            if (bias2) bv += bias2[col];
            C[(size_t)orow * N + col] = acc[i][j] + bv;
        }
    }
}

// ---------------- recurrent gates: C = init + h(128xK) * W(NxK)^T ----------
// 64x64 tile, 256 threads, 4x4 micro-tile (more blocks for the tiny M=128 GEMM)
__global__ void gates_gemm_kernel(const float* __restrict__ A,
                                  const float* __restrict__ Bm,
                                  const float* __restrict__ init,
                                  float* __restrict__ C,
                                  int N, int K) {
    __shared__ float As[16][64];
    __shared__ float Bs[16][64];
    const int tid = threadIdx.x;          // 256 threads
    const int tx = tid & 15, ty = tid >> 4;
    const int m0 = blockIdx.y * 64, n0 = blockIdx.x * 64;

    float acc[4][4];
#pragma unroll
    for (int i = 0; i < 4; i++)
#pragma unroll
        for (int j = 0; j < 4; j++) acc[i][j] = 0.f;

    for (int kt = 0; kt < K; kt += 16) {
        int r  = tid >> 2;                 // 0..63
        int k4 = (tid & 3) << 2;
        float4 va = *reinterpret_cast<const float4*>(A + (size_t)(m0 + r) * K + kt + k4);
        As[k4 + 0][r] = va.x; As[k4 + 1][r] = va.y;
        As[k4 + 2][r] = va.z; As[k4 + 3][r] = va.w;
        float4 vb = *reinterpret_cast<const float4*>(Bm + (size_t)(n0 + r) * K + kt + k4);
        Bs[k4 + 0][r] = vb.x; Bs[k4 + 1][r] = vb.y;
        Bs[k4 + 2][r] = vb.z; Bs[k4 + 3][r] = vb.w;
        __syncthreads();
#pragma unroll
        for (int k = 0; k < 16; k++) {
            float4 a0 = *reinterpret_cast<const float4*>(&As[k][ty * 4]);
            float4 b0 = *reinterpret_cast<const float4*>(&Bs[k][tx * 4]);
            float a[4] = {a0.x, a0.y, a0.z, a0.w};
            float b[4] = {b0.x, b0.y, b0.z, b0.w};
#pragma unroll
            for (int i = 0; i < 4; i++)
#pragma unroll
                for (int j = 0; j < 4; j++) acc[i][j] = fmaf(a[i], b[j], acc[i][j]);
        }
        __syncthreads();
    }

#pragma unroll
    for (int i = 0; i < 4; i++) {
        int r = m0 + ty * 4 + i;
#pragma unroll
        for (int j = 0; j < 4; j++) {
            int col = n0 + tx * 4 + j;
            C[(size_t)r * N + col] = init[(size_t)r * N + col] + acc[i][j];
        }
    }
}

// ---------------- LSTM cell -------------------------------------------------
__device__ __forceinline__ float sigmoidf_(float x) { return 1.f / (1.f + expf(-x)); }

__global__ void lstm_cell_kernel(const float* __restrict__ gates,
                                 float* __restrict__ h,
                                 float* __restrict__ c,
                                 float* __restrict__ ys_t) {
    int idx = blockIdx.x * blockDim.x + threadIdx.x;
    if (idx >= Bdim * Hdim) return;
    int b = idx / Hdim, j = idx % Hdim;
    const float* g = gates + (size_t)b * G4;
    float i_ = sigmoidf_(g[j]);
    float f_ = sigmoidf_(g[Hdim + j]);
    float gg = tanhf(g[2 * Hdim + j]);
    float o_ = sigmoidf_(g[3 * Hdim + j]);
    float cn = f_ * c[idx] + i_ * gg;
    c[idx] = cn;
    float hn = o_ * tanhf(cn);
    h[idx] = hn;
    ys_t[idx] = hn;
}

// ---------------- launcher ---------------------------------------------------
extern "C" void kernel_launch(void* const* d_in, const int* in_sizes, int n_in,
                              void* d_out, int out_size) {
    const int*   src   = (const int*)  d_in[0];
    const int*   trg   = (const int*)  d_in[1];
    const float* bert  = (const float*)d_in[2];
    const float* emb   = (const float*)d_in[3];
    const float* W_ih  = (const float*)d_in[4];
    const float* W_hh  = (const float*)d_in[5];
    const float* b_ih  = (const float*)d_in[6];
    const float* b_hh  = (const float*)d_in[7];
    const float* W_out = (const float*)d_in[8];
    const float* b_out = (const float*)d_in[9];
    float* out = (float*)d_out;

    float *xs, *ys0, *ys1, *xproj, *h, *c, *gates;
    cudaGetSymbolAddress((void**)&xs,    g_xs);
    cudaGetSymbolAddress((void**)&ys0,   g_ys0);
    cudaGetSymbolAddress((void**)&ys1,   g_ys1);
    cudaGetSymbolAddress((void**)&xproj, g_xproj);
    cudaGetSymbolAddress((void**)&h,     g_h);
    cudaGetSymbolAddress((void**)&c,     g_c);
    cudaGetSymbolAddress((void**)&gates, g_gates);

    // 1. embed targets -> xs[t][b][h]
    embed_trg_kernel<<<(Tdim * Bdim * Hdim + 255) / 256, 256>>>(trg, emb, xs);

    // 2. two LSTM layers; input projections hoisted into one big GEMM per layer
    for (int l = 0; l < Ldim; l++) {
        const float* Wi = W_ih + (size_t)l * G4 * Hdim;
        const float* Wh = W_hh + (size_t)l * G4 * Hdim;
        const float* bi = b_ih + (size_t)l * G4;
        const float* bh = b_hh + (size_t)l * G4;
        const float* inp = (l == 0) ? xs : ys0;
        float* ys = (l == 0) ? ys0 : ys1;

        // xproj[t,b,:] = inp[t,b,:] @ Wi^T + bi + bh   (8192 x 3072, K=768)
        sgemm128_kernel<false><<<dim3(G4 / 128, (Tdim * Bdim) / 128), 256>>>(
            inp, Wi, xproj, G4, Hdim, bi, bh);

        // reset recurrent state for this layer
        init_h_kernel<<<(Bdim * Hdim + 255) / 256, 256>>>(src, bert, h, c);

        // serial recurrence over T
        for (int t = 0; t < Tdim; t++) {
            gates_gemm_kernel<<<dim3(G4 / 64, Bdim / 64), 256>>>(
                h, Wh, xproj + (size_t)t * Bdim * G4, gates, G4, Hdim);
            lstm_cell_kernel<<<(Bdim * Hdim + 255) / 256, 256>>>(
                gates, h, c, ys + (size_t)t * Bdim * Hdim);
        }
    }

    // 3. logits: out[b,t,v] = ys1[t,b,:] . W_out[v,:] + b_out[v]
    sgemm128_kernel<true><<<dim3(Vdim / 128, (Tdim * Bdim) / 128), 256>>>(
        ys1, W_out, out, Vdim, Hdim, b_out, nullptr);
}